// round 7
// baseline (speedup 1.0000x reference)
#include <cuda_runtime.h>
#include <math.h>
#include <stdint.h>

#define BATCH 32
#define HGT 64
#define WID 64
#define CDIM 256
#define MTOT (BATCH*HGT*WID)   /* 131072 rows */
#define COUT_FULL 516

// ---------------- scratch (device globals: no allocation allowed) -----------
__device__ float g_q   [(size_t)MTOT*CDIM];   // clipped query
__device__ float g_c0  [(size_t)MTOT*CDIM];   // context -> gated acc (dw7 out)
__device__ float g_c1  [(size_t)MTOT*CDIM];   // ctx1
__device__ float g_acc [(size_t)MTOT*CDIM];   // ctx2
__device__ float g_gates[(size_t)MTOT*4];     // clipped gates
__device__ float g_partial[BATCH*32*CDIM];    // per-tile partial sums of ctx3
__device__ float g_mean[BATCH*CDIM];          // tanh(mean)

__device__ __forceinline__ float gelu_f(float x){
    return 0.5f*x*(1.0f+erff(x*0.70710678118654752440f));
}
__device__ __forceinline__ float clipf(float v, float lim){
    return fminf(fmaxf(v, -lim), lim);
}
__device__ __forceinline__ unsigned f2tf(float f){
    unsigned u; asm("cvt.rna.tf32.f32 %0, %1;" : "=r"(u) : "f"(f)); return u;
}
__device__ __forceinline__ void mma_tf32(float* c, const unsigned* a,
                                         unsigned b0, unsigned b1){
    asm volatile("mma.sync.aligned.m16n8k8.row.col.f32.tf32.tf32.f32 "
        "{%0,%1,%2,%3},{%4,%5,%6,%7},{%8,%9},{%0,%1,%2,%3};"
        : "+f"(c[0]),"+f"(c[1]),"+f"(c[2]),"+f"(c[3])
        : "r"(a[0]),"r"(a[1]),"r"(a[2]),"r"(a[3]),"r"(b0),"r"(b1));
}

#define G0_SMEM_WORDS  (128*36 + 32*260)            /* 51712 B  */
#define G12_SMEM_WORDS (128*36 + 32*260 + 128*260)  /* 184832 B */

// ---------------- GEMM0: x @ w_init, 128x256 block, 512 thr, K=256 ----------
// grid.x=2: cols 0..255 -> g_q (clip100), cols 256..511 -> g_c0 (context).
// Block x==1 also computes gates (cols 512..515) from the As smem tile.
__global__ __launch_bounds__(512)
void gemm0_k(const float* __restrict__ Aext, const float* __restrict__ Bw,
             const float* __restrict__ bias)
{
    extern __shared__ unsigned sh[];
    unsigned (*As)[36]  = (unsigned(*)[36])sh;             // 128 x 36
    unsigned (*Bs)[260] = (unsigned(*)[260])(sh + 128*36); // 32 x 260
    __shared__ float Wg[32][4];

    int t    = threadIdx.x;
    int lane = t & 31, wid = t >> 5;
    int wm   = (wid & 3) * 32;
    int wn   = (wid >> 2) * 64;
    int qid  = lane >> 2, tid4 = lane & 3;

    int row0 = blockIdx.y * 128;
    int col0 = blockIdx.x * 256;

    int a_r  = t >> 3;
    int a_c4 = t & 7;
    int b_k  = t >> 6;
    int b_c4 = t & 63;

    float4 aS[2], bS[4];

#define LOAD_T0(kt)                                                            \
  {                                                                            \
    int kb = (kt)*32;                                                          \
    _Pragma("unroll")                                                          \
    for (int i=0;i<2;i++)                                                      \
      aS[i] = *(const float4*)(Aext + (size_t)(row0 + a_r + 64*i)*CDIM         \
                               + kb + a_c4*4);                                 \
    _Pragma("unroll")                                                          \
    for (int i=0;i<4;i++)                                                      \
      bS[i] = *(const float4*)(Bw + (size_t)(kb + b_k + 8*i)*COUT_FULL         \
                               + col0 + b_c4*4);                               \
  }

    float acc[2][8][4];
    #pragma unroll
    for (int mt=0;mt<2;mt++)
      #pragma unroll
      for (int nt=0;nt<8;nt++)
        #pragma unroll
        for (int j=0;j<4;j++) acc[mt][nt][j] = 0.f;

    const bool gate_block = (blockIdx.x==1);
    int   g_r = t >> 2, g_c = t & 3;
    float ga  = 0.f;

    LOAD_T0(0);

    for (int kt = 0; kt < 8; kt++) {
        __syncthreads();
        #pragma unroll
        for (int i=0;i<2;i++){
            uint4 u = make_uint4(f2tf(aS[i].x), f2tf(aS[i].y),
                                 f2tf(aS[i].z), f2tf(aS[i].w));
            *(uint4*)&As[a_r + 64*i][a_c4*4] = u;
        }
        #pragma unroll
        for (int i=0;i<4;i++){
            uint4 u = make_uint4(f2tf(bS[i].x), f2tf(bS[i].y),
                                 f2tf(bS[i].z), f2tf(bS[i].w));
            *(uint4*)&Bs[b_k + 8*i][b_c4*4] = u;
        }
        if (gate_block && t < 128) {
            int k = t >> 2, c = t & 3;
            Wg[k][c] = Bw[(size_t)(kt*32 + k)*COUT_FULL + 512 + c];
        }
        __syncthreads();
        if (kt < 7) LOAD_T0(kt+1);

        if (gate_block) {
            #pragma unroll
            for (int k=0;k<32;k++)
                ga = fmaf(__uint_as_float(As[g_r][k]), Wg[k][g_c], ga);
        }

        #pragma unroll
        for (int ks=0; ks<32; ks+=8){
            unsigned a[2][4];
            #pragma unroll
            for (int mt=0; mt<2; mt++){
                int r = wm + mt*16 + qid;
                a[mt][0] = As[r    ][ks+tid4];
                a[mt][1] = As[r + 8][ks+tid4];
                a[mt][2] = As[r    ][ks+tid4+4];
                a[mt][3] = As[r + 8][ks+tid4+4];
            }
            #pragma unroll
            for (int nt=0; nt<8; nt++){
                int c = wn + nt*8 + qid;
                unsigned b0 = Bs[ks+tid4  ][c];
                unsigned b1 = Bs[ks+tid4+4][c];
                mma_tf32(acc[0][nt], a[0], b0, b1);
                mma_tf32(acc[1][nt], a[1], b0, b1);
            }
        }
    }
#undef LOAD_T0

    if (gate_block) {
        g_gates[(size_t)(row0 + g_r)*4 + g_c] = clipf(ga + bias[512 + g_c], 1.f);
    }

    #pragma unroll
    for (int mt=0;mt<2;mt++){
        int r0r = row0 + wm + mt*16 + qid;
        #pragma unroll
        for (int nt=0;nt<8;nt++){
            int c  = col0 + wn + nt*8 + tid4*2;
            float bb0 = bias[c], bb1 = bias[c+1];
            float v0 = acc[mt][nt][0] + bb0;
            float v1 = acc[mt][nt][1] + bb1;
            float v2 = acc[mt][nt][2] + bb0;
            float v3 = acc[mt][nt][3] + bb1;
            if (c < CDIM) {
                *(float2*)&g_q[(size_t)r0r*CDIM + c] =
                    make_float2(clipf(v0,100.f), clipf(v1,100.f));
                *(float2*)&g_q[(size_t)(r0r+8)*CDIM + c] =
                    make_float2(clipf(v2,100.f), clipf(v3,100.f));
            } else {
                int cc = c - CDIM;
                *(float2*)&g_c0[(size_t)r0r*CDIM + cc] = make_float2(v0, v1);
                *(float2*)&g_c0[(size_t)(r0r+8)*CDIM + cc] = make_float2(v2, v3);
            }
        }
    }
}

// ---------------- fused GEMM1+GEMM2: one block = 128 rows, full N=256 -------
// Stage 1: mod = (acc + mean*g3) @ w_mod + b_mod ; t = clip(mod,100)*q -> smem
// Stage 2: out = t @ w_proj + b_proj  (t read from smem, tf32)
__global__ __launch_bounds__(512)
void gemm12_k(const float* __restrict__ w_mod, const float* __restrict__ b_mod,
              const float* __restrict__ w_proj, const float* __restrict__ b_proj,
              float* __restrict__ outext)
{
    extern __shared__ unsigned sh[];
    unsigned (*As)[36]   = (unsigned(*)[36])sh;                        // 128x36
    unsigned (*Bs)[260]  = (unsigned(*)[260])(sh + 128*36);            // 32x260
    unsigned (*As2)[260] = (unsigned(*)[260])(sh + 128*36 + 32*260);   // 128x260

    int t    = threadIdx.x;
    int lane = t & 31, wid = t >> 5;
    int wm   = (wid & 3) * 32;
    int wn   = (wid >> 2) * 64;
    int qid  = lane >> 2, tid4 = lane & 3;

    int row0 = blockIdx.x * 128;

    int a_r  = t >> 3;
    int a_c4 = t & 7;
    int b_k  = t >> 6;
    int b_c4 = t & 63;

    float4 aS[2], bS[4];
    float g3[2];
    g3[0] = g_gates[(size_t)(row0 + a_r     )*4 + 3];
    g3[1] = g_gates[(size_t)(row0 + a_r + 64)*4 + 3];

#define LOAD_A1(kt)                                                            \
  {                                                                            \
    int kb = (kt)*32;                                                          \
    _Pragma("unroll")                                                          \
    for (int i=0;i<2;i++){                                                     \
      int r = row0 + a_r + 64*i;                                               \
      float4 v  = *(const float4*)(g_c0 + (size_t)r*CDIM + kb + a_c4*4);       \
      float4 mv = *(const float4*)(g_mean + (size_t)(r>>12)*CDIM + kb + a_c4*4);\
      v.x = fmaf(mv.x,g3[i],v.x); v.y = fmaf(mv.y,g3[i],v.y);                  \
      v.z = fmaf(mv.z,g3[i],v.z); v.w = fmaf(mv.w,g3[i],v.w);                  \
      aS[i] = v;                                                               \
    }                                                                          \
  }
#define LOAD_B(W,kt)                                                           \
  {                                                                            \
    int kb = (kt)*32;                                                          \
    _Pragma("unroll")                                                          \
    for (int i=0;i<4;i++)                                                      \
      bS[i] = *(const float4*)((W) + (size_t)(kb + b_k + 8*i)*CDIM + b_c4*4);  \
  }

    float acc[2][8][4];
    #pragma unroll
    for (int mt=0;mt<2;mt++)
      #pragma unroll
      for (int nt=0;nt<8;nt++)
        #pragma unroll
        for (int j=0;j<4;j++) acc[mt][nt][j] = 0.f;

    LOAD_A1(0); LOAD_B(w_mod, 0);

    // ---- stage 1 ----
    for (int kt = 0; kt < 8; kt++) {
        __syncthreads();
        #pragma unroll
        for (int i=0;i<2;i++){
            uint4 u = make_uint4(f2tf(aS[i].x), f2tf(aS[i].y),
                                 f2tf(aS[i].z), f2tf(aS[i].w));
            *(uint4*)&As[a_r + 64*i][a_c4*4] = u;
        }
        #pragma unroll
        for (int i=0;i<4;i++){
            uint4 u = make_uint4(f2tf(bS[i].x), f2tf(bS[i].y),
                                 f2tf(bS[i].z), f2tf(bS[i].w));
            *(uint4*)&Bs[b_k + 8*i][b_c4*4] = u;
        }
        __syncthreads();
        if (kt < 7) { LOAD_A1(kt+1); LOAD_B(w_mod, kt+1); }

        #pragma unroll
        for (int ks=0; ks<32; ks+=8){
            unsigned a[2][4];
            #pragma unroll
            for (int mt=0; mt<2; mt++){
                int r = wm + mt*16 + qid;
                a[mt][0] = As[r    ][ks+tid4];
                a[mt][1] = As[r + 8][ks+tid4];
                a[mt][2] = As[r    ][ks+tid4+4];
                a[mt][3] = As[r + 8][ks+tid4+4];
            }
            #pragma unroll
            for (int nt=0; nt<8; nt++){
                int c = wn + nt*8 + qid;
                unsigned b0 = Bs[ks+tid4  ][c];
                unsigned b1 = Bs[ks+tid4+4][c];
                mma_tf32(acc[0][nt], a[0], b0, b1);
                mma_tf32(acc[1][nt], a[1], b0, b1);
            }
        }
    }

    // ---- epilogue 1: t = clip(mod,100)*q -> As2 (tf32), reset acc ----
    #pragma unroll
    for (int mt=0;mt<2;mt++){
        int rl = wm + mt*16 + qid;
        int rg = row0 + rl;
        #pragma unroll
        for (int nt=0;nt<8;nt++){
            int c  = wn + nt*8 + tid4*2;
            float bb0 = b_mod[c], bb1 = b_mod[c+1];
            float2 qa = *(const float2*)&g_q[(size_t)rg*CDIM + c];
            float2 qb = *(const float2*)&g_q[(size_t)(rg+8)*CDIM + c];
            As2[rl  ][c  ] = f2tf(clipf(acc[mt][nt][0]+bb0,100.f)*qa.x);
            As2[rl  ][c+1] = f2tf(clipf(acc[mt][nt][1]+bb1,100.f)*qa.y);
            As2[rl+8][c  ] = f2tf(clipf(acc[mt][nt][2]+bb0,100.f)*qb.x);
            As2[rl+8][c+1] = f2tf(clipf(acc[mt][nt][3]+bb1,100.f)*qb.y);
            acc[mt][nt][0]=0.f; acc[mt][nt][1]=0.f;
            acc[mt][nt][2]=0.f; acc[mt][nt][3]=0.f;
        }
    }

    LOAD_B(w_proj, 0);

    // ---- stage 2 ----
    for (int kt = 0; kt < 8; kt++) {
        __syncthreads();   // kt=0: also guards As2 writes
        #pragma unroll
        for (int i=0;i<4;i++){
            uint4 u = make_uint4(f2tf(bS[i].x), f2tf(bS[i].y),
                                 f2tf(bS[i].z), f2tf(bS[i].w));
            *(uint4*)&Bs[b_k + 8*i][b_c4*4] = u;
        }
        __syncthreads();
        if (kt < 7) LOAD_B(w_proj, kt+1);

        #pragma unroll
        for (int ks=0; ks<32; ks+=8){
            int kk = kt*32 + ks;
            unsigned a[2][4];
            #pragma unroll
            for (int mt=0; mt<2; mt++){
                int r = wm + mt*16 + qid;
                a[mt][0] = As2[r    ][kk+tid4];
                a[mt][1] = As2[r + 8][kk+tid4];
                a[mt][2] = As2[r    ][kk+tid4+4];
                a[mt][3] = As2[r + 8][kk+tid4+4];
            }
            #pragma unroll
            for (int nt=0; nt<8; nt++){
                int c = wn + nt*8 + qid;
                unsigned b0 = Bs[ks+tid4  ][c];
                unsigned b1 = Bs[ks+tid4+4][c];
                mma_tf32(acc[0][nt], a[0], b0, b1);
                mma_tf32(acc[1][nt], a[1], b0, b1);
            }
        }
    }
#undef LOAD_A1
#undef LOAD_B

    // ---- epilogue 2: out = t @ w_proj + b_proj ----
    #pragma unroll
    for (int mt=0;mt<2;mt++){
        int r0r = row0 + wm + mt*16 + qid;
        #pragma unroll
        for (int nt=0;nt<8;nt++){
            int c  = wn + nt*8 + tid4*2;
            float bb0 = b_proj[c], bb1 = b_proj[c+1];
            *(float2*)&outext[(size_t)r0r*CDIM + c] =
                make_float2(acc[mt][nt][0]+bb0, acc[mt][nt][1]+bb1);
            *(float2*)&outext[(size_t)(r0r+8)*CDIM + c] =
                make_float2(acc[mt][nt][2]+bb0, acc[mt][nt][3]+bb1);
        }
    }
}

// ---------------- depthwise conv SxS + gelu -------------------------------
// LEVEL 0: g_c0 -> g_c1   (ctx1)
// LEVEL 1: g_c1 -> g_acc  (ctx2)
// LEVEL 2: g_acc -> g_c0 = ctx1*g0 + ctx2*g1 + ctx3*g2 ; + mean partials(ctx3)
template<int S, int LEVEL>
__global__ __launch_bounds__(256)
void dwconv_k(const float* __restrict__ kern)
{
    constexpr int P = S/2;
    constexpr int TH = 16, TW = 8, CF = 8;
    constexpr int HH = TH + S - 1, HW2 = TW + S - 1;
    const float* in = (LEVEL==0) ? g_c0 : (LEVEL==1) ? g_c1 : g_acc;
    float* out      = (LEVEL==0) ? g_c1 : (LEVEL==1) ? g_acc : g_c0;

    __shared__ float4 sIn[HH*HW2][CF];
    __shared__ float4 sK[S*S][CF];

    int t  = threadIdx.x;
    int w0 = blockIdx.x * TW;
    int h0 = blockIdx.y * TH;
    int z  = blockIdx.z;
    int b  = z >> 3;
    int c0 = (z & 7) * 32;

    for (int i = t; i < S*S*CF; i += 256) {
        int f = i & 7, p = i >> 3;
        sK[p][f] = *(const float4*)(kern + p*CDIM + c0 + f*4);
    }
    for (int i = t; i < HH*HW2*CF; i += 256) {
        int f = i & 7, p = i >> 3;
        int hy = p / HW2, hx = p % HW2;
        int ih = h0 - P + hy, iw = w0 - P + hx;
        float4 v = make_float4(0.f,0.f,0.f,0.f);
        if (ih >= 0 && ih < HGT && iw >= 0 && iw < WID)
            v = *(const float4*)(in + ((size_t)((b*HGT+ih)*WID+iw))*CDIM + c0 + f*4);
        sIn[p][f] = v;
    }
    __syncthreads();

    int f  = t & 7;
    int ox = (t >> 3) & 7;
    int yq = t >> 6;

    float4 acc[4];
    #pragma unroll
    for (int i=0;i<4;i++) acc[i] = make_float4(0.f,0.f,0.f,0.f);

    #pragma unroll
    for (int kw = 0; kw < S; kw++) {
        float4 kv[S];
        #pragma unroll
        for (int kh = 0; kh < S; kh++) kv[kh] = sK[kh*S+kw][f];
        #pragma unroll
        for (int r = 0; r < 4 + S - 1; r++) {
            float4 iv = sIn[(yq*4 + r)*HW2 + ox + kw][f];
            #pragma unroll
            for (int kh = 0; kh < S; kh++) {
                int oy = r - kh;
                if (oy >= 0 && oy < 4) {
                    acc[oy].x = fmaf(iv.x, kv[kh].x, acc[oy].x);
                    acc[oy].y = fmaf(iv.y, kv[kh].y, acc[oy].y);
                    acc[oy].z = fmaf(iv.z, kv[kh].z, acc[oy].z);
                    acc[oy].w = fmaf(iv.w, kv[kh].w, acc[oy].w);
                }
            }
        }
    }

    float4 s = make_float4(0.f,0.f,0.f,0.f);
    #pragma unroll
    for (int oy = 0; oy < 4; oy++) {
        float4 v = acc[oy];
        v.x = gelu_f(v.x); v.y = gelu_f(v.y);
        v.z = gelu_f(v.z); v.w = gelu_f(v.w);
        size_t row = (size_t)(b*HGT + h0 + yq*4 + oy)*WID + (w0 + ox);
        size_t idx = row*CDIM + c0 + f*4;
        if (LEVEL < 2) {
            *(float4*)(out + idx) = v;
        } else {
            s.x += v.x; s.y += v.y; s.z += v.z; s.w += v.w;
            // ctx2 = center input pixel (already in smem halo)
            float4 c2 = sIn[(yq*4 + oy + P)*HW2 + ox + P][f];
            float4 c1 = *(const float4*)(g_c1 + idx);
            float4 gt = *(const float4*)&g_gates[row*4];
            float4 o;
            o.x = fmaf(v.x,gt.z, fmaf(c2.x,gt.y, c1.x*gt.x));
            o.y = fmaf(v.y,gt.z, fmaf(c2.y,gt.y, c1.y*gt.x));
            o.z = fmaf(v.z,gt.z, fmaf(c2.z,gt.y, c1.z*gt.x));
            o.w = fmaf(v.w,gt.z, fmaf(c2.w,gt.y, c1.w*gt.x));
            *(float4*)(out + idx) = o;
        }
    }

    if (LEVEL == 2) {
        // deterministic per-block spatial partial sum of ctx3 (reuse sIn)
        float4* red = (float4*)&sIn[0][0];
        __syncthreads();
        red[t] = s;
        __syncthreads();
        #pragma unroll
        for (int st = 128; st >= 8; st >>= 1) {
            if (t < st) {
                float4 a = red[t], bb = red[t+st];
                red[t] = make_float4(a.x+bb.x, a.y+bb.y, a.z+bb.z, a.w+bb.w);
            }
            __syncthreads();
        }
        if (t < 8) {
            int tile = blockIdx.y * 8 + blockIdx.x;   // 0..31
            *(float4*)&g_partial[((size_t)(b*32 + tile))*CDIM + c0 + t*4] = red[t];
        }
    }
}

// ---------------- final mean: sum 32 tiles, tanh --------------------------
__global__ void mean_final_k()
{
    int b = blockIdx.x, c = threadIdx.x;
    float s = 0.f;
    #pragma unroll
    for (int i = 0; i < 32; i++) s += g_partial[(size_t)(b*32 + i)*CDIM + c];
    g_mean[b*CDIM + c] = tanhf(s * (1.0f/4096.0f));
}

// ---------------- launch ----------------------------------------------------
extern "C" void kernel_launch(void* const* d_in, const int* in_sizes, int n_in,
                              void* d_out, int out_size)
{
    const float* x      = (const float*)d_in[0];
    const float* w_init = (const float*)d_in[1];
    const float* b_init = (const float*)d_in[2];
    const float* k0     = (const float*)d_in[3];
    const float* k1     = (const float*)d_in[4];
    const float* k2     = (const float*)d_in[5];
    const float* w_mod  = (const float*)d_in[6];
    const float* b_mod  = (const float*)d_in[7];
    const float* w_proj = (const float*)d_in[8];
    const float* b_proj = (const float*)d_in[9];
    float* out = (float*)d_out;

    const int smem0  = G0_SMEM_WORDS * 4;
    const int smem12 = G12_SMEM_WORDS * 4;
    cudaFuncSetAttribute(gemm0_k,  cudaFuncAttributeMaxDynamicSharedMemorySize, smem0);
    cudaFuncSetAttribute(gemm12_k, cudaFuncAttributeMaxDynamicSharedMemorySize, smem12);

    // 1. x @ w_init -> query(clip)->g_q, context->g_c0, gates->g_gates
    gemm0_k<<<dim3(2, MTOT/128), 512, smem0>>>(x, w_init, b_init);

    // 2-4. focal levels; L2 also forms gated acc + mean partials
    dim3 cg(WID/8, HGT/16, BATCH*8);
    dwconv_k<3,0><<<cg, 256>>>(k0);
    dwconv_k<5,1><<<cg, 256>>>(k1);
    dwconv_k<7,2><<<cg, 256>>>(k2);

    // 5. tanh(mean)
    mean_final_k<<<BATCH, 256>>>();

    // 6. fused: mod GEMM -> t = clip(mod)*q (smem) -> out = t @ w_proj
    gemm12_k<<<MTOT/128, 512, smem12>>>(w_mod, b_mod, w_proj, b_proj, out);
}

// round 8
// speedup vs baseline: 1.1023x; 1.1023x over previous
#include <cuda_runtime.h>
#include <math.h>
#include <stdint.h>

#define BATCH 32
#define HGT 64
#define WID 64
#define CDIM 256
#define MTOT (BATCH*HGT*WID)   /* 131072 rows */
#define COUT_FULL 516

// ---------------- scratch (device globals: no allocation allowed) -----------
__device__ float g_q   [(size_t)MTOT*CDIM];   // clipped query
__device__ float g_c0  [(size_t)MTOT*CDIM];   // context -> ctx3
__device__ float g_c1  [(size_t)MTOT*CDIM];   // ctx1
__device__ float g_acc [(size_t)MTOT*CDIM];   // ctx2
__device__ float g_gates[(size_t)MTOT*4];     // clipped gates
__device__ float g_partial[BATCH*32*CDIM];    // per-tile partial sums of ctx3
__device__ float g_mean[BATCH*CDIM];          // tanh(mean)

__device__ __forceinline__ float gelu_f(float x){
    return 0.5f*x*(1.0f+erff(x*0.70710678118654752440f));
}
__device__ __forceinline__ float clipf(float v, float lim){
    return fminf(fmaxf(v, -lim), lim);
}
__device__ __forceinline__ unsigned f2tf(float f){
    unsigned u; asm("cvt.rna.tf32.f32 %0, %1;" : "=r"(u) : "f"(f)); return u;
}
__device__ __forceinline__ void mma_tf32(float* c, const unsigned* a,
                                         unsigned b0, unsigned b1){
    asm volatile("mma.sync.aligned.m16n8k8.row.col.f32.tf32.tf32.f32 "
        "{%0,%1,%2,%3},{%4,%5,%6,%7},{%8,%9},{%0,%1,%2,%3};"
        : "+f"(c[0]),"+f"(c[1]),"+f"(c[2]),"+f"(c[3])
        : "r"(a[0]),"r"(a[1]),"r"(a[2]),"r"(a[3]),"r"(b0),"r"(b1));
}

#define G0_SMEM_WORDS  (128*36 + 32*260)            /* 51712 B  */
#define G12_SMEM_WORDS (128*36 + 32*260 + 128*260)  /* 184832 B */

// ---------------- GEMM0: x @ w_init, 128x256 block, 512 thr, K=256 ----------
// grid.x=2: cols 0..255 -> g_q (clip100), cols 256..511 -> g_c0 (context).
// Block x==1 also computes gates (cols 512..515) from the As smem tile.
__global__ __launch_bounds__(512)
void gemm0_k(const float* __restrict__ Aext, const float* __restrict__ Bw,
             const float* __restrict__ bias)
{
    extern __shared__ unsigned sh[];
    unsigned (*As)[36]  = (unsigned(*)[36])sh;             // 128 x 36
    unsigned (*Bs)[260] = (unsigned(*)[260])(sh + 128*36); // 32 x 260
    __shared__ float Wg[32][4];

    int t    = threadIdx.x;
    int lane = t & 31, wid = t >> 5;
    int wm   = (wid & 3) * 32;
    int wn   = (wid >> 2) * 64;
    int qid  = lane >> 2, tid4 = lane & 3;

    int row0 = blockIdx.y * 128;
    int col0 = blockIdx.x * 256;

    int a_r  = t >> 3;
    int a_c4 = t & 7;
    int b_k  = t >> 6;
    int b_c4 = t & 63;

    float4 aS[2], bS[4];

#define LOAD_T0(kt)                                                            \
  {                                                                            \
    int kb = (kt)*32;                                                          \
    _Pragma("unroll")                                                          \
    for (int i=0;i<2;i++)                                                      \
      aS[i] = *(const float4*)(Aext + (size_t)(row0 + a_r + 64*i)*CDIM         \
                               + kb + a_c4*4);                                 \
    _Pragma("unroll")                                                          \
    for (int i=0;i<4;i++)                                                      \
      bS[i] = *(const float4*)(Bw + (size_t)(kb + b_k + 8*i)*COUT_FULL         \
                               + col0 + b_c4*4);                               \
  }

    float acc[2][8][4];
    #pragma unroll
    for (int mt=0;mt<2;mt++)
      #pragma unroll
      for (int nt=0;nt<8;nt++)
        #pragma unroll
        for (int j=0;j<4;j++) acc[mt][nt][j] = 0.f;

    const bool gate_block = (blockIdx.x==1);
    int   g_r = t >> 2, g_c = t & 3;
    float ga  = 0.f;

    LOAD_T0(0);

    for (int kt = 0; kt < 8; kt++) {
        __syncthreads();
        #pragma unroll
        for (int i=0;i<2;i++){
            uint4 u = make_uint4(f2tf(aS[i].x), f2tf(aS[i].y),
                                 f2tf(aS[i].z), f2tf(aS[i].w));
            *(uint4*)&As[a_r + 64*i][a_c4*4] = u;
        }
        #pragma unroll
        for (int i=0;i<4;i++){
            uint4 u = make_uint4(f2tf(bS[i].x), f2tf(bS[i].y),
                                 f2tf(bS[i].z), f2tf(bS[i].w));
            *(uint4*)&Bs[b_k + 8*i][b_c4*4] = u;
        }
        if (gate_block && t < 128) {
            int k = t >> 2, c = t & 3;
            Wg[k][c] = Bw[(size_t)(kt*32 + k)*COUT_FULL + 512 + c];
        }
        __syncthreads();
        if (kt < 7) LOAD_T0(kt+1);

        if (gate_block) {
            #pragma unroll
            for (int k=0;k<32;k++)
                ga = fmaf(__uint_as_float(As[g_r][k]), Wg[k][g_c], ga);
        }

        #pragma unroll
        for (int ks=0; ks<32; ks+=8){
            unsigned a[2][4];
            #pragma unroll
            for (int mt=0; mt<2; mt++){
                int r = wm + mt*16 + qid;
                a[mt][0] = As[r    ][ks+tid4];
                a[mt][1] = As[r + 8][ks+tid4];
                a[mt][2] = As[r    ][ks+tid4+4];
                a[mt][3] = As[r + 8][ks+tid4+4];
            }
            #pragma unroll
            for (int nt=0; nt<8; nt++){
                int c = wn + nt*8 + qid;
                unsigned b0 = Bs[ks+tid4  ][c];
                unsigned b1 = Bs[ks+tid4+4][c];
                mma_tf32(acc[0][nt], a[0], b0, b1);
                mma_tf32(acc[1][nt], a[1], b0, b1);
            }
        }
    }
#undef LOAD_T0

    if (gate_block) {
        g_gates[(size_t)(row0 + g_r)*4 + g_c] = clipf(ga + bias[512 + g_c], 1.f);
    }

    #pragma unroll
    for (int mt=0;mt<2;mt++){
        int r0r = row0 + wm + mt*16 + qid;
        #pragma unroll
        for (int nt=0;nt<8;nt++){
            int c  = col0 + wn + nt*8 + tid4*2;
            float bb0 = bias[c], bb1 = bias[c+1];
            float v0 = acc[mt][nt][0] + bb0;
            float v1 = acc[mt][nt][1] + bb1;
            float v2 = acc[mt][nt][2] + bb0;
            float v3 = acc[mt][nt][3] + bb1;
            if (c < CDIM) {
                *(float2*)&g_q[(size_t)r0r*CDIM + c] =
                    make_float2(clipf(v0,100.f), clipf(v1,100.f));
                *(float2*)&g_q[(size_t)(r0r+8)*CDIM + c] =
                    make_float2(clipf(v2,100.f), clipf(v3,100.f));
            } else {
                int cc = c - CDIM;
                *(float2*)&g_c0[(size_t)r0r*CDIM + cc] = make_float2(v0, v1);
                *(float2*)&g_c0[(size_t)(r0r+8)*CDIM + cc] = make_float2(v2, v3);
            }
        }
    }
}

// ---------------- fused GEMM1+GEMM2: one block = 128 rows, full N=256 -------
// Stage 1: mod = (ctx1*g0+ctx2*g1+ctx3*g2+mean*g3) @ w_mod + b_mod ;
//          t = clip(mod,100)*q -> smem (tf32)
// Stage 2: out = t @ w_proj + b_proj
__global__ __launch_bounds__(512)
void gemm12_k(const float* __restrict__ w_mod, const float* __restrict__ b_mod,
              const float* __restrict__ w_proj, const float* __restrict__ b_proj,
              float* __restrict__ outext)
{
    extern __shared__ unsigned sh[];
    unsigned (*As)[36]   = (unsigned(*)[36])sh;                        // 128x36
    unsigned (*Bs)[260]  = (unsigned(*)[260])(sh + 128*36);            // 32x260
    unsigned (*As2)[260] = (unsigned(*)[260])(sh + 128*36 + 32*260);   // 128x260

    int t    = threadIdx.x;
    int lane = t & 31, wid = t >> 5;
    int wm   = (wid & 3) * 32;
    int wn   = (wid >> 2) * 64;
    int qid  = lane >> 2, tid4 = lane & 3;

    int row0 = blockIdx.x * 128;

    int a_r  = t >> 3;
    int a_c4 = t & 7;
    int b_k  = t >> 6;
    int b_c4 = t & 63;

    float4 aS[2], bS[4];
    float4 gv[2];
    gv[0] = *(const float4*)&g_gates[(size_t)(row0 + a_r     )*4];
    gv[1] = *(const float4*)&g_gates[(size_t)(row0 + a_r + 64)*4];

#define LOAD_A1(kt)                                                            \
  {                                                                            \
    int kb = (kt)*32;                                                          \
    _Pragma("unroll")                                                          \
    for (int i=0;i<2;i++){                                                     \
      int r = row0 + a_r + 64*i;                                               \
      size_t off = (size_t)r*CDIM + kb + a_c4*4;                               \
      float4 v1 = *(const float4*)(g_c1  + off);                               \
      float4 v2 = *(const float4*)(g_acc + off);                               \
      float4 v3 = *(const float4*)(g_c0  + off);                               \
      float4 mv = *(const float4*)(g_mean + (size_t)(r>>12)*CDIM + kb + a_c4*4);\
      float4 g = gv[i];                                                        \
      float4 v;                                                                \
      v.x = fmaf(mv.x,g.w, fmaf(v3.x,g.z, fmaf(v2.x,g.y, v1.x*g.x)));          \
      v.y = fmaf(mv.y,g.w, fmaf(v3.y,g.z, fmaf(v2.y,g.y, v1.y*g.x)));          \
      v.z = fmaf(mv.z,g.w, fmaf(v3.z,g.z, fmaf(v2.z,g.y, v1.z*g.x)));          \
      v.w = fmaf(mv.w,g.w, fmaf(v3.w,g.z, fmaf(v2.w,g.y, v1.w*g.x)));          \
      aS[i] = v;                                                               \
    }                                                                          \
  }
#define LOAD_B(W,kt)                                                           \
  {                                                                            \
    int kb = (kt)*32;                                                          \
    _Pragma("unroll")                                                          \
    for (int i=0;i<4;i++)                                                      \
      bS[i] = *(const float4*)((W) + (size_t)(kb + b_k + 8*i)*CDIM + b_c4*4);  \
  }

    float acc[2][8][4];
    #pragma unroll
    for (int mt=0;mt<2;mt++)
      #pragma unroll
      for (int nt=0;nt<8;nt++)
        #pragma unroll
        for (int j=0;j<4;j++) acc[mt][nt][j] = 0.f;

    LOAD_A1(0); LOAD_B(w_mod, 0);

    // ---- stage 1 ----
    for (int kt = 0; kt < 8; kt++) {
        __syncthreads();
        #pragma unroll
        for (int i=0;i<2;i++){
            uint4 u = make_uint4(f2tf(aS[i].x), f2tf(aS[i].y),
                                 f2tf(aS[i].z), f2tf(aS[i].w));
            *(uint4*)&As[a_r + 64*i][a_c4*4] = u;
        }
        #pragma unroll
        for (int i=0;i<4;i++){
            uint4 u = make_uint4(f2tf(bS[i].x), f2tf(bS[i].y),
                                 f2tf(bS[i].z), f2tf(bS[i].w));
            *(uint4*)&Bs[b_k + 8*i][b_c4*4] = u;
        }
        __syncthreads();
        if (kt < 7) { LOAD_A1(kt+1); LOAD_B(w_mod, kt+1); }

        #pragma unroll
        for (int ks=0; ks<32; ks+=8){
            unsigned a[2][4];
            #pragma unroll
            for (int mt=0; mt<2; mt++){
                int r = wm + mt*16 + qid;
                a[mt][0] = As[r    ][ks+tid4];
                a[mt][1] = As[r + 8][ks+tid4];
                a[mt][2] = As[r    ][ks+tid4+4];
                a[mt][3] = As[r + 8][ks+tid4+4];
            }
            #pragma unroll
            for (int nt=0; nt<8; nt++){
                int c = wn + nt*8 + qid;
                unsigned b0 = Bs[ks+tid4  ][c];
                unsigned b1 = Bs[ks+tid4+4][c];
                mma_tf32(acc[0][nt], a[0], b0, b1);
                mma_tf32(acc[1][nt], a[1], b0, b1);
            }
        }
    }

    // ---- epilogue 1: t = clip(mod,100)*q -> As2 (tf32), reset acc ----
    #pragma unroll
    for (int mt=0;mt<2;mt++){
        int rl = wm + mt*16 + qid;
        int rg = row0 + rl;
        #pragma unroll
        for (int nt=0;nt<8;nt++){
            int c  = wn + nt*8 + tid4*2;
            float bb0 = b_mod[c], bb1 = b_mod[c+1];
            float2 qa = *(const float2*)&g_q[(size_t)rg*CDIM + c];
            float2 qb = *(const float2*)&g_q[(size_t)(rg+8)*CDIM + c];
            As2[rl  ][c  ] = f2tf(clipf(acc[mt][nt][0]+bb0,100.f)*qa.x);
            As2[rl  ][c+1] = f2tf(clipf(acc[mt][nt][1]+bb1,100.f)*qa.y);
            As2[rl+8][c  ] = f2tf(clipf(acc[mt][nt][2]+bb0,100.f)*qb.x);
            As2[rl+8][c+1] = f2tf(clipf(acc[mt][nt][3]+bb1,100.f)*qb.y);
            acc[mt][nt][0]=0.f; acc[mt][nt][1]=0.f;
            acc[mt][nt][2]=0.f; acc[mt][nt][3]=0.f;
        }
    }

    LOAD_B(w_proj, 0);

    // ---- stage 2 ----
    for (int kt = 0; kt < 8; kt++) {
        __syncthreads();   // kt=0: also guards As2 writes
        #pragma unroll
        for (int i=0;i<4;i++){
            uint4 u = make_uint4(f2tf(bS[i].x), f2tf(bS[i].y),
                                 f2tf(bS[i].z), f2tf(bS[i].w));
            *(uint4*)&Bs[b_k + 8*i][b_c4*4] = u;
        }
        __syncthreads();
        if (kt < 7) LOAD_B(w_proj, kt+1);

        #pragma unroll
        for (int ks=0; ks<32; ks+=8){
            int kk = kt*32 + ks;
            unsigned a[2][4];
            #pragma unroll
            for (int mt=0; mt<2; mt++){
                int r = wm + mt*16 + qid;
                a[mt][0] = As2[r    ][kk+tid4];
                a[mt][1] = As2[r + 8][kk+tid4];
                a[mt][2] = As2[r    ][kk+tid4+4];
                a[mt][3] = As2[r + 8][kk+tid4+4];
            }
            #pragma unroll
            for (int nt=0; nt<8; nt++){
                int c = wn + nt*8 + qid;
                unsigned b0 = Bs[ks+tid4  ][c];
                unsigned b1 = Bs[ks+tid4+4][c];
                mma_tf32(acc[0][nt], a[0], b0, b1);
                mma_tf32(acc[1][nt], a[1], b0, b1);
            }
        }
    }
#undef LOAD_A1
#undef LOAD_B

    // ---- epilogue 2: out = t @ w_proj + b_proj ----
    #pragma unroll
    for (int mt=0;mt<2;mt++){
        int r0r = row0 + wm + mt*16 + qid;
        #pragma unroll
        for (int nt=0;nt<8;nt++){
            int c  = wn + nt*8 + tid4*2;
            float bb0 = b_proj[c], bb1 = b_proj[c+1];
            *(float2*)&outext[(size_t)r0r*CDIM + c] =
                make_float2(acc[mt][nt][0]+bb0, acc[mt][nt][1]+bb1);
            *(float2*)&outext[(size_t)(r0r+8)*CDIM + c] =
                make_float2(acc[mt][nt][2]+bb0, acc[mt][nt][3]+bb1);
        }
    }
}

// ---------------- depthwise conv SxS + gelu (16x16 spatial x 16ch) ----------
// LEVEL 0: g_c0 -> g_c1   (ctx1)
// LEVEL 1: g_c1 -> g_acc  (ctx2)
// LEVEL 2: g_acc -> g_c0  (ctx3, plain) + per-block spatial partial sums
template<int S, int LEVEL>
__global__ __launch_bounds__(256)
void dwconv_k(const float* __restrict__ kern)
{
    constexpr int P = S/2;
    constexpr int TH = 16, TW = 16, CF = 4;
    constexpr int HH = TH + S - 1, HW2 = TW + S - 1;
    const float* in = (LEVEL==0) ? g_c0 : (LEVEL==1) ? g_c1 : g_acc;
    float* out      = (LEVEL==0) ? g_c1 : (LEVEL==1) ? g_acc : g_c0;

    __shared__ float4 sIn[HH*HW2][CF];
    __shared__ float4 sK[S*S][CF];

    int t  = threadIdx.x;
    int w0 = blockIdx.x * TW;
    int h0 = blockIdx.y * TH;
    int z  = blockIdx.z;
    int b  = z >> 4;
    int c0 = (z & 15) * 16;

    for (int i = t; i < S*S*CF; i += 256) {
        int f = i & 3, p = i >> 2;
        sK[p][f] = *(const float4*)(kern + p*CDIM + c0 + f*4);
    }
    for (int i = t; i < HH*HW2*CF; i += 256) {
        int f = i & 3, p = i >> 2;
        int hy = p / HW2, hx = p % HW2;
        int ih = h0 - P + hy, iw = w0 - P + hx;
        float4 v = make_float4(0.f,0.f,0.f,0.f);
        if (ih >= 0 && ih < HGT && iw >= 0 && iw < WID)
            v = *(const float4*)(in + ((size_t)((b*HGT+ih)*WID+iw))*CDIM + c0 + f*4);
        sIn[p][f] = v;
    }
    __syncthreads();

    int f  = t & 3;
    int ox = (t >> 2) & 15;
    int yq = t >> 6;          // 0..3, each handles 4 y rows

    float4 acc[4];
    #pragma unroll
    for (int i=0;i<4;i++) acc[i] = make_float4(0.f,0.f,0.f,0.f);

    #pragma unroll
    for (int kw = 0; kw < S; kw++) {
        float4 kv[S];
        #pragma unroll
        for (int kh = 0; kh < S; kh++) kv[kh] = sK[kh*S+kw][f];
        #pragma unroll
        for (int r = 0; r < 4 + S - 1; r++) {
            float4 iv = sIn[(yq*4 + r)*HW2 + ox + kw][f];
            #pragma unroll
            for (int kh = 0; kh < S; kh++) {
                int oy = r - kh;
                if (oy >= 0 && oy < 4) {
                    acc[oy].x = fmaf(iv.x, kv[kh].x, acc[oy].x);
                    acc[oy].y = fmaf(iv.y, kv[kh].y, acc[oy].y);
                    acc[oy].z = fmaf(iv.z, kv[kh].z, acc[oy].z);
                    acc[oy].w = fmaf(iv.w, kv[kh].w, acc[oy].w);
                }
            }
        }
    }

    float4 s = make_float4(0.f,0.f,0.f,0.f);
    #pragma unroll
    for (int oy = 0; oy < 4; oy++) {
        float4 v = acc[oy];
        v.x = gelu_f(v.x); v.y = gelu_f(v.y);
        v.z = gelu_f(v.z); v.w = gelu_f(v.w);
        size_t row = (size_t)(b*HGT + h0 + yq*4 + oy)*WID + (w0 + ox);
        *(float4*)(out + row*CDIM + c0 + f*4) = v;
        if (LEVEL == 2) {
            s.x += v.x; s.y += v.y; s.z += v.z; s.w += v.w;
        }
    }

    if (LEVEL == 2) {
        // deterministic per-block spatial partial sum (reuse sIn as scratch)
        // tree strides are multiples of 4 so channel lane f is preserved
        float4* red = (float4*)&sIn[0][0];
        __syncthreads();
        red[t] = s;
        __syncthreads();
        #pragma unroll
        for (int st = 128; st >= 4; st >>= 1) {
            if (t < st) {
                float4 a = red[t], bb = red[t+st];
                red[t] = make_float4(a.x+bb.x, a.y+bb.y, a.z+bb.z, a.w+bb.w);
            }
            __syncthreads();
        }
        if (t < 4) {
            int tile = blockIdx.y * 4 + blockIdx.x;   // 0..15
            *(float4*)&g_partial[((size_t)(b*16 + tile))*CDIM + c0 + t*4] = red[t];
        }
    }
}

// ---------------- final mean: sum 16 tiles, tanh --------------------------
__global__ void mean_final_k()
{
    int b = blockIdx.x, c = threadIdx.x;
    float s = 0.f;
    #pragma unroll
    for (int i = 0; i < 16; i++) s += g_partial[(size_t)(b*16 + i)*CDIM + c];
    g_mean[b*CDIM + c] = tanhf(s * (1.0f/4096.0f));
}

// ---------------- launch ----------------------------------------------------
extern "C" void kernel_launch(void* const* d_in, const int* in_sizes, int n_in,
                              void* d_out, int out_size)
{
    const float* x      = (const float*)d_in[0];
    const float* w_init = (const float*)d_in[1];
    const float* b_init = (const float*)d_in[2];
    const float* k0     = (const float*)d_in[3];
    const float* k1     = (const float*)d_in[4];
    const float* k2     = (const float*)d_in[5];
    const float* w_mod  = (const float*)d_in[6];
    const float* b_mod  = (const float*)d_in[7];
    const float* w_proj = (const float*)d_in[8];
    const float* b_proj = (const float*)d_in[9];
    float* out = (float*)d_out;

    const int smem0  = G0_SMEM_WORDS * 4;
    const int smem12 = G12_SMEM_WORDS * 4;
    cudaFuncSetAttribute(gemm0_k,  cudaFuncAttributeMaxDynamicSharedMemorySize, smem0);
    cudaFuncSetAttribute(gemm12_k, cudaFuncAttributeMaxDynamicSharedMemorySize, smem12);

    // 1. x @ w_init -> query(clip)->g_q, context->g_c0, gates->g_gates
    gemm0_k<<<dim3(2, MTOT/128), 512, smem0>>>(x, w_init, b_init);

    // 2-4. focal levels (pure conv+gelu; L2 emits mean partials)
    dim3 cg(WID/16, HGT/16, BATCH*16);
    dwconv_k<3,0><<<cg, 256>>>(k0);
    dwconv_k<5,1><<<cg, 256>>>(k1);
    dwconv_k<7,2><<<cg, 256>>>(k2);

    // 5. tanh(mean)
    mean_final_k<<<BATCH, 256>>>();

    // 6. fused: mod GEMM (gated-sum A) -> t = clip(mod)*q -> out = t @ w_proj
    gemm12_k<<<MTOT/128, 512, smem12>>>(w_mod, b_mod, w_proj, b_proj, out);
}

// round 9
// speedup vs baseline: 1.1239x; 1.0197x over previous
#include <cuda_runtime.h>
#include <math.h>
#include <stdint.h>

#define BATCH 32
#define HGT 64
#define WID 64
#define CDIM 256
#define MTOT (BATCH*HGT*WID)   /* 131072 rows */
#define COUT_FULL 516

// ---------------- scratch (device globals: no allocation allowed) -----------
__device__ float g_q   [(size_t)MTOT*CDIM];   // clipped query
__device__ float g_c0  [(size_t)MTOT*CDIM];   // context -> ctx3
__device__ float g_c1  [(size_t)MTOT*CDIM];   // ctx1
__device__ float g_acc [(size_t)MTOT*CDIM];   // ctx2
__device__ float g_gates[(size_t)MTOT*4];     // clipped gates
__device__ float g_partial[BATCH*32*CDIM];    // per-tile partial sums of ctx3
__device__ float g_mean[BATCH*CDIM];          // tanh(mean)

__device__ __forceinline__ float gelu_f(float x){
    return 0.5f*x*(1.0f+erff(x*0.70710678118654752440f));
}
__device__ __forceinline__ float clipf(float v, float lim){
    return fminf(fmaxf(v, -lim), lim);
}
__device__ __forceinline__ unsigned f2tf(float f){
    unsigned u; asm("cvt.rna.tf32.f32 %0, %1;" : "=r"(u) : "f"(f)); return u;
}
__device__ __forceinline__ void mma_tf32(float* c, const unsigned* a,
                                         unsigned b0, unsigned b1){
    asm volatile("mma.sync.aligned.m16n8k8.row.col.f32.tf32.tf32.f32 "
        "{%0,%1,%2,%3},{%4,%5,%6,%7},{%8,%9},{%0,%1,%2,%3};"
        : "+f"(c[0]),"+f"(c[1]),"+f"(c[2]),"+f"(c[3])
        : "r"(a[0]),"r"(a[1]),"r"(a[2]),"r"(a[3]),"r"(b0),"r"(b1));
}

// ---- packed f32x2 helpers (Blackwell FFMA2; ptxas won't emit it itself) ----
__device__ __forceinline__ void fma_x2(unsigned long long& d,
                                       unsigned long long a,
                                       unsigned long long b){
    asm("fma.rn.f32x2 %0, %1, %2, %0;" : "+l"(d) : "l"(a), "l"(b));
}
__device__ __forceinline__ float2 ull_to_f2(unsigned long long u){
    float2 f; asm("mov.b64 {%0,%1}, %2;" : "=f"(f.x), "=f"(f.y) : "l"(u));
    return f;
}

#define G0_SMEM_WORDS  (128*36 + 32*260)            /* 51712 B  */
#define G12_SMEM_WORDS (128*36 + 32*260 + 128*260)  /* 184832 B */

// ---------------- GEMM0: x @ w_init, 128x256 block, 512 thr, K=256 ----------
// grid.x=2: cols 0..255 -> g_q (clip100), cols 256..511 -> g_c0 (context).
// Block x==1 also computes gates (cols 512..515) from the As smem tile.
__global__ __launch_bounds__(512)
void gemm0_k(const float* __restrict__ Aext, const float* __restrict__ Bw,
             const float* __restrict__ bias)
{
    extern __shared__ unsigned sh[];
    unsigned (*As)[36]  = (unsigned(*)[36])sh;             // 128 x 36
    unsigned (*Bs)[260] = (unsigned(*)[260])(sh + 128*36); // 32 x 260
    __shared__ float Wg[32][4];

    int t    = threadIdx.x;
    int lane = t & 31, wid = t >> 5;
    int wm   = (wid & 3) * 32;
    int wn   = (wid >> 2) * 64;
    int qid  = lane >> 2, tid4 = lane & 3;

    int row0 = blockIdx.y * 128;
    int col0 = blockIdx.x * 256;

    int a_r  = t >> 3;
    int a_c4 = t & 7;
    int b_k  = t >> 6;
    int b_c4 = t & 63;

    float4 aS[2], bS[4];

#define LOAD_T0(kt)                                                            \
  {                                                                            \
    int kb = (kt)*32;                                                          \
    _Pragma("unroll")                                                          \
    for (int i=0;i<2;i++)                                                      \
      aS[i] = *(const float4*)(Aext + (size_t)(row0 + a_r + 64*i)*CDIM         \
                               + kb + a_c4*4);                                 \
    _Pragma("unroll")                                                          \
    for (int i=0;i<4;i++)                                                      \
      bS[i] = *(const float4*)(Bw + (size_t)(kb + b_k + 8*i)*COUT_FULL         \
                               + col0 + b_c4*4);                               \
  }

    float acc[2][8][4];
    #pragma unroll
    for (int mt=0;mt<2;mt++)
      #pragma unroll
      for (int nt=0;nt<8;nt++)
        #pragma unroll
        for (int j=0;j<4;j++) acc[mt][nt][j] = 0.f;

    const bool gate_block = (blockIdx.x==1);
    int   g_r = t >> 2, g_c = t & 3;
    float ga  = 0.f;

    LOAD_T0(0);

    for (int kt = 0; kt < 8; kt++) {
        __syncthreads();
        #pragma unroll
        for (int i=0;i<2;i++){
            uint4 u = make_uint4(f2tf(aS[i].x), f2tf(aS[i].y),
                                 f2tf(aS[i].z), f2tf(aS[i].w));
            *(uint4*)&As[a_r + 64*i][a_c4*4] = u;
        }
        #pragma unroll
        for (int i=0;i<4;i++){
            uint4 u = make_uint4(f2tf(bS[i].x), f2tf(bS[i].y),
                                 f2tf(bS[i].z), f2tf(bS[i].w));
            *(uint4*)&Bs[b_k + 8*i][b_c4*4] = u;
        }
        if (gate_block && t < 128) {
            int k = t >> 2, c = t & 3;
            Wg[k][c] = Bw[(size_t)(kt*32 + k)*COUT_FULL + 512 + c];
        }
        __syncthreads();
        if (kt < 7) LOAD_T0(kt+1);

        if (gate_block) {
            #pragma unroll
            for (int k=0;k<32;k++)
                ga = fmaf(__uint_as_float(As[g_r][k]), Wg[k][g_c], ga);
        }

        #pragma unroll
        for (int ks=0; ks<32; ks+=8){
            unsigned a[2][4];
            #pragma unroll
            for (int mt=0; mt<2; mt++){
                int r = wm + mt*16 + qid;
                a[mt][0] = As[r    ][ks+tid4];
                a[mt][1] = As[r + 8][ks+tid4];
                a[mt][2] = As[r    ][ks+tid4+4];
                a[mt][3] = As[r + 8][ks+tid4+4];
            }
            #pragma unroll
            for (int nt=0; nt<8; nt++){
                int c = wn + nt*8 + qid;
                unsigned b0 = Bs[ks+tid4  ][c];
                unsigned b1 = Bs[ks+tid4+4][c];
                mma_tf32(acc[0][nt], a[0], b0, b1);
                mma_tf32(acc[1][nt], a[1], b0, b1);
            }
        }
    }
#undef LOAD_T0

    if (gate_block) {
        g_gates[(size_t)(row0 + g_r)*4 + g_c] = clipf(ga + bias[512 + g_c], 1.f);
    }

    #pragma unroll
    for (int mt=0;mt<2;mt++){
        int r0r = row0 + wm + mt*16 + qid;
        #pragma unroll
        for (int nt=0;nt<8;nt++){
            int c  = col0 + wn + nt*8 + tid4*2;
            float bb0 = bias[c], bb1 = bias[c+1];
            float v0 = acc[mt][nt][0] + bb0;
            float v1 = acc[mt][nt][1] + bb1;
            float v2 = acc[mt][nt][2] + bb0;
            float v3 = acc[mt][nt][3] + bb1;
            if (c < CDIM) {
                *(float2*)&g_q[(size_t)r0r*CDIM + c] =
                    make_float2(clipf(v0,100.f), clipf(v1,100.f));
                *(float2*)&g_q[(size_t)(r0r+8)*CDIM + c] =
                    make_float2(clipf(v2,100.f), clipf(v3,100.f));
            } else {
                int cc = c - CDIM;
                *(float2*)&g_c0[(size_t)r0r*CDIM + cc] = make_float2(v0, v1);
                *(float2*)&g_c0[(size_t)(r0r+8)*CDIM + cc] = make_float2(v2, v3);
            }
        }
    }
}

// ---------------- fused GEMM1+GEMM2: one block = 128 rows, full N=256 -------
// Stage 1: mod = (ctx1*g0+ctx2*g1+ctx3*g2+mean*g3) @ w_mod + b_mod ;
//          t = clip(mod,100)*q -> smem (tf32)
// Stage 2: out = t @ w_proj + b_proj
__global__ __launch_bounds__(512)
void gemm12_k(const float* __restrict__ w_mod, const float* __restrict__ b_mod,
              const float* __restrict__ w_proj, const float* __restrict__ b_proj,
              float* __restrict__ outext)
{
    extern __shared__ unsigned sh[];
    unsigned (*As)[36]   = (unsigned(*)[36])sh;                        // 128x36
    unsigned (*Bs)[260]  = (unsigned(*)[260])(sh + 128*36);            // 32x260
    unsigned (*As2)[260] = (unsigned(*)[260])(sh + 128*36 + 32*260);   // 128x260

    int t    = threadIdx.x;
    int lane = t & 31, wid = t >> 5;
    int wm   = (wid & 3) * 32;
    int wn   = (wid >> 2) * 64;
    int qid  = lane >> 2, tid4 = lane & 3;

    int row0 = blockIdx.x * 128;

    int a_r  = t >> 3;
    int a_c4 = t & 7;
    int b_k  = t >> 6;
    int b_c4 = t & 63;

    float4 aS[2], bS[4];
    float4 gv[2];
    gv[0] = *(const float4*)&g_gates[(size_t)(row0 + a_r     )*4];
    gv[1] = *(const float4*)&g_gates[(size_t)(row0 + a_r + 64)*4];

#define LOAD_A1(kt)                                                            \
  {                                                                            \
    int kb = (kt)*32;                                                          \
    _Pragma("unroll")                                                          \
    for (int i=0;i<2;i++){                                                     \
      int r = row0 + a_r + 64*i;                                               \
      size_t off = (size_t)r*CDIM + kb + a_c4*4;                               \
      float4 v1 = *(const float4*)(g_c1  + off);                               \
      float4 v2 = *(const float4*)(g_acc + off);                               \
      float4 v3 = *(const float4*)(g_c0  + off);                               \
      float4 mv = *(const float4*)(g_mean + (size_t)(r>>12)*CDIM + kb + a_c4*4);\
      float4 g = gv[i];                                                        \
      float4 v;                                                                \
      v.x = fmaf(mv.x,g.w, fmaf(v3.x,g.z, fmaf(v2.x,g.y, v1.x*g.x)));          \
      v.y = fmaf(mv.y,g.w, fmaf(v3.y,g.z, fmaf(v2.y,g.y, v1.y*g.x)));          \
      v.z = fmaf(mv.z,g.w, fmaf(v3.z,g.z, fmaf(v2.z,g.y, v1.z*g.x)));          \
      v.w = fmaf(mv.w,g.w, fmaf(v3.w,g.z, fmaf(v2.w,g.y, v1.w*g.x)));          \
      aS[i] = v;                                                               \
    }                                                                          \
  }
#define LOAD_B(W,kt)                                                           \
  {                                                                            \
    int kb = (kt)*32;                                                          \
    _Pragma("unroll")                                                          \
    for (int i=0;i<4;i++)                                                      \
      bS[i] = *(const float4*)((W) + (size_t)(kb + b_k + 8*i)*CDIM + b_c4*4);  \
  }

    float acc[2][8][4];
    #pragma unroll
    for (int mt=0;mt<2;mt++)
      #pragma unroll
      for (int nt=0;nt<8;nt++)
        #pragma unroll
        for (int j=0;j<4;j++) acc[mt][nt][j] = 0.f;

    LOAD_A1(0); LOAD_B(w_mod, 0);

    // ---- stage 1 ----
    for (int kt = 0; kt < 8; kt++) {
        __syncthreads();
        #pragma unroll
        for (int i=0;i<2;i++){
            uint4 u = make_uint4(f2tf(aS[i].x), f2tf(aS[i].y),
                                 f2tf(aS[i].z), f2tf(aS[i].w));
            *(uint4*)&As[a_r + 64*i][a_c4*4] = u;
        }
        #pragma unroll
        for (int i=0;i<4;i++){
            uint4 u = make_uint4(f2tf(bS[i].x), f2tf(bS[i].y),
                                 f2tf(bS[i].z), f2tf(bS[i].w));
            *(uint4*)&Bs[b_k + 8*i][b_c4*4] = u;
        }
        __syncthreads();
        if (kt < 7) { LOAD_A1(kt+1); LOAD_B(w_mod, kt+1); }

        #pragma unroll
        for (int ks=0; ks<32; ks+=8){
            unsigned a[2][4];
            #pragma unroll
            for (int mt=0; mt<2; mt++){
                int r = wm + mt*16 + qid;
                a[mt][0] = As[r    ][ks+tid4];
                a[mt][1] = As[r + 8][ks+tid4];
                a[mt][2] = As[r    ][ks+tid4+4];
                a[mt][3] = As[r + 8][ks+tid4+4];
            }
            #pragma unroll
            for (int nt=0; nt<8; nt++){
                int c = wn + nt*8 + qid;
                unsigned b0 = Bs[ks+tid4  ][c];
                unsigned b1 = Bs[ks+tid4+4][c];
                mma_tf32(acc[0][nt], a[0], b0, b1);
                mma_tf32(acc[1][nt], a[1], b0, b1);
            }
        }
    }

    // ---- epilogue 1: t = clip(mod,100)*q -> As2 (tf32), reset acc ----
    #pragma unroll
    for (int mt=0;mt<2;mt++){
        int rl = wm + mt*16 + qid;
        int rg = row0 + rl;
        #pragma unroll
        for (int nt=0;nt<8;nt++){
            int c  = wn + nt*8 + tid4*2;
            float bb0 = b_mod[c], bb1 = b_mod[c+1];
            float2 qa = *(const float2*)&g_q[(size_t)rg*CDIM + c];
            float2 qb = *(const float2*)&g_q[(size_t)(rg+8)*CDIM + c];
            As2[rl  ][c  ] = f2tf(clipf(acc[mt][nt][0]+bb0,100.f)*qa.x);
            As2[rl  ][c+1] = f2tf(clipf(acc[mt][nt][1]+bb1,100.f)*qa.y);
            As2[rl+8][c  ] = f2tf(clipf(acc[mt][nt][2]+bb0,100.f)*qb.x);
            As2[rl+8][c+1] = f2tf(clipf(acc[mt][nt][3]+bb1,100.f)*qb.y);
            acc[mt][nt][0]=0.f; acc[mt][nt][1]=0.f;
            acc[mt][nt][2]=0.f; acc[mt][nt][3]=0.f;
        }
    }

    LOAD_B(w_proj, 0);

    // ---- stage 2 ----
    for (int kt = 0; kt < 8; kt++) {
        __syncthreads();   // kt=0: also guards As2 writes
        #pragma unroll
        for (int i=0;i<4;i++){
            uint4 u = make_uint4(f2tf(bS[i].x), f2tf(bS[i].y),
                                 f2tf(bS[i].z), f2tf(bS[i].w));
            *(uint4*)&Bs[b_k + 8*i][b_c4*4] = u;
        }
        __syncthreads();
        if (kt < 7) LOAD_B(w_proj, kt+1);

        #pragma unroll
        for (int ks=0; ks<32; ks+=8){
            int kk = kt*32 + ks;
            unsigned a[2][4];
            #pragma unroll
            for (int mt=0; mt<2; mt++){
                int r = wm + mt*16 + qid;
                a[mt][0] = As2[r    ][kk+tid4];
                a[mt][1] = As2[r + 8][kk+tid4];
                a[mt][2] = As2[r    ][kk+tid4+4];
                a[mt][3] = As2[r + 8][kk+tid4+4];
            }
            #pragma unroll
            for (int nt=0; nt<8; nt++){
                int c = wn + nt*8 + qid;
                unsigned b0 = Bs[ks+tid4  ][c];
                unsigned b1 = Bs[ks+tid4+4][c];
                mma_tf32(acc[0][nt], a[0], b0, b1);
                mma_tf32(acc[1][nt], a[1], b0, b1);
            }
        }
    }
#undef LOAD_A1
#undef LOAD_B

    // ---- epilogue 2: out = t @ w_proj + b_proj ----
    #pragma unroll
    for (int mt=0;mt<2;mt++){
        int r0r = row0 + wm + mt*16 + qid;
        #pragma unroll
        for (int nt=0;nt<8;nt++){
            int c  = wn + nt*8 + tid4*2;
            float bb0 = b_proj[c], bb1 = b_proj[c+1];
            *(float2*)&outext[(size_t)r0r*CDIM + c] =
                make_float2(acc[mt][nt][0]+bb0, acc[mt][nt][1]+bb1);
            *(float2*)&outext[(size_t)(r0r+8)*CDIM + c] =
                make_float2(acc[mt][nt][2]+bb0, acc[mt][nt][3]+bb1);
        }
    }
}

// ---------------- depthwise conv SxS + gelu (16x16 spatial x 16ch) ----------
// Inner product uses packed fma.rn.f32x2 (FFMA2): half the FMA issue slots.
// LEVEL 0: g_c0 -> g_c1   (ctx1)
// LEVEL 1: g_c1 -> g_acc  (ctx2)
// LEVEL 2: g_acc -> g_c0  (ctx3, plain) + per-block spatial partial sums
template<int S, int LEVEL>
__global__ __launch_bounds__(256)
void dwconv_k(const float* __restrict__ kern)
{
    constexpr int P = S/2;
    constexpr int TH = 16, TW = 16, CF = 4;
    constexpr int HH = TH + S - 1, HW2 = TW + S - 1;
    const float* in = (LEVEL==0) ? g_c0 : (LEVEL==1) ? g_c1 : g_acc;
    float* out      = (LEVEL==0) ? g_c1 : (LEVEL==1) ? g_acc : g_c0;

    __shared__ float4 sIn[HH*HW2][CF];
    __shared__ float4 sK[S*S][CF];

    int t  = threadIdx.x;
    int w0 = blockIdx.x * TW;
    int h0 = blockIdx.y * TH;
    int z  = blockIdx.z;
    int b  = z >> 4;
    int c0 = (z & 15) * 16;

    for (int i = t; i < S*S*CF; i += 256) {
        int f = i & 3, p = i >> 2;
        sK[p][f] = *(const float4*)(kern + p*CDIM + c0 + f*4);
    }
    for (int i = t; i < HH*HW2*CF; i += 256) {
        int f = i & 3, p = i >> 2;
        int hy = p / HW2, hx = p % HW2;
        int ih = h0 - P + hy, iw = w0 - P + hx;
        float4 v = make_float4(0.f,0.f,0.f,0.f);
        if (ih >= 0 && ih < HGT && iw >= 0 && iw < WID)
            v = *(const float4*)(in + ((size_t)((b*HGT+ih)*WID+iw))*CDIM + c0 + f*4);
        sIn[p][f] = v;
    }
    __syncthreads();

    int f  = t & 3;
    int ox = (t >> 2) & 15;
    int yq = t >> 6;          // 0..3, each handles 4 y rows

    ulonglong2 acc2[4];
    #pragma unroll
    for (int i=0;i<4;i++){ acc2[i].x = 0ull; acc2[i].y = 0ull; }

    #pragma unroll
    for (int kw = 0; kw < S; kw++) {
        ulonglong2 kv[S];
        #pragma unroll
        for (int kh = 0; kh < S; kh++)
            kv[kh] = *(const ulonglong2*)&sK[kh*S+kw][f];
        #pragma unroll
        for (int r = 0; r < 4 + S - 1; r++) {
            ulonglong2 iv = *(const ulonglong2*)&sIn[(yq*4 + r)*HW2 + ox + kw][f];
            #pragma unroll
            for (int kh = 0; kh < S; kh++) {
                int oy = r - kh;
                if (oy >= 0 && oy < 4) {
                    fma_x2(acc2[oy].x, iv.x, kv[kh].x);
                    fma_x2(acc2[oy].y, iv.y, kv[kh].y);
                }
            }
        }
    }

    float4 s = make_float4(0.f,0.f,0.f,0.f);
    #pragma unroll
    for (int oy = 0; oy < 4; oy++) {
        float2 lo = ull_to_f2(acc2[oy].x);
        float2 hi = ull_to_f2(acc2[oy].y);
        float4 v;
        v.x = gelu_f(lo.x); v.y = gelu_f(lo.y);
        v.z = gelu_f(hi.x); v.w = gelu_f(hi.y);
        size_t row = (size_t)(b*HGT + h0 + yq*4 + oy)*WID + (w0 + ox);
        *(float4*)(out + row*CDIM + c0 + f*4) = v;
        if (LEVEL == 2) {
            s.x += v.x; s.y += v.y; s.z += v.z; s.w += v.w;
        }
    }

    if (LEVEL == 2) {
        // deterministic per-block spatial partial sum (reuse sIn as scratch)
        // tree strides are multiples of 4 so channel lane f is preserved
        float4* red = (float4*)&sIn[0][0];
        __syncthreads();
        red[t] = s;
        __syncthreads();
        #pragma unroll
        for (int st = 128; st >= 4; st >>= 1) {
            if (t < st) {
                float4 a = red[t], bb = red[t+st];
                red[t] = make_float4(a.x+bb.x, a.y+bb.y, a.z+bb.z, a.w+bb.w);
            }
            __syncthreads();
        }
        if (t < 4) {
            int tile = blockIdx.y * 4 + blockIdx.x;   // 0..15
            *(float4*)&g_partial[((size_t)(b*16 + tile))*CDIM + c0 + t*4] = red[t];
        }
    }
}

// ---------------- final mean: sum 16 tiles, tanh --------------------------
__global__ void mean_final_k()
{
    int b = blockIdx.x, c = threadIdx.x;
    float s = 0.f;
    #pragma unroll
    for (int i = 0; i < 16; i++) s += g_partial[(size_t)(b*16 + i)*CDIM + c];
    g_mean[b*CDIM + c] = tanhf(s * (1.0f/4096.0f));
}

// ---------------- launch ----------------------------------------------------
extern "C" void kernel_launch(void* const* d_in, const int* in_sizes, int n_in,
                              void* d_out, int out_size)
{
    const float* x      = (const float*)d_in[0];
    const float* w_init = (const float*)d_in[1];
    const float* b_init = (const float*)d_in[2];
    const float* k0     = (const float*)d_in[3];
    const float* k1     = (const float*)d_in[4];
    const float* k2     = (const float*)d_in[5];
    const float* w_mod  = (const float*)d_in[6];
    const float* b_mod  = (const float*)d_in[7];
    const float* w_proj = (const float*)d_in[8];
    const float* b_proj = (const float*)d_in[9];
    float* out = (float*)d_out;

    const int smem0  = G0_SMEM_WORDS * 4;
    const int smem12 = G12_SMEM_WORDS * 4;
    cudaFuncSetAttribute(gemm0_k,  cudaFuncAttributeMaxDynamicSharedMemorySize, smem0);
    cudaFuncSetAttribute(gemm12_k, cudaFuncAttributeMaxDynamicSharedMemorySize, smem12);

    // 1. x @ w_init -> query(clip)->g_q, context->g_c0, gates->g_gates
    gemm0_k<<<dim3(2, MTOT/128), 512, smem0>>>(x, w_init, b_init);

    // 2-4. focal levels (pure conv+gelu; L2 emits mean partials)
    dim3 cg(WID/16, HGT/16, BATCH*16);
    dwconv_k<3,0><<<cg, 256>>>(k0);
    dwconv_k<5,1><<<cg, 256>>>(k1);
    dwconv_k<7,2><<<cg, 256>>>(k2);

    // 5. tanh(mean)
    mean_final_k<<<BATCH, 256>>>();

    // 6. fused: mod GEMM (gated-sum A) -> t = clip(mod)*q -> out = t @ w_proj
    gemm12_k<<<MTOT/128, 512, smem12>>>(w_mod, b_mod, w_proj, b_proj, out);
}